// round 5
// baseline (speedup 1.0000x reference)
#include <cuda_runtime.h>
#include <math.h>

#define BB 4
#define NND 4096
#define EED 131072

// ---------------- scratch ----------------
__device__ float  d_stats[3 * 512];
__device__ float  d_xn  [BB * NND * 32];
__device__ float2 d_T   [BB * 64 * 16 * 32];
__device__ float2 d_Xft [BB * 32 * 16 * 32];
__device__ float2 d_oft [BB * 32 * 16 * 32];
__device__ float2 d_V   [BB * 64 * 16 * 32];
__device__ float  d_x1  [BB * NND * 32];
__device__ float  d_x1b [BB * NND * 32];
__device__ float  d_x2  [BB * NND * 32];
__device__ float  d_h   [EED * 64];
__device__ float  d_g   [BB * NND * 64 * 32];
__device__ float  d_msg [(long long)EED * BB * 32];
__device__ int    d_esrc[EED];
__device__ int    d_edst[EED];
__device__ int    d_is64;
__device__ int    d_cnt [2 * NND];
__device__ int    d_offA[2 * (NND + 1)];
__device__ int    d_cur [2 * NND];
__device__ int    d_eid [2 * EED];

__device__ __forceinline__ float gelu_f(float x) {
    return 0.5f * x * (1.0f + erff(x * 0.70710678118654752f));
}

// ---------------- edge index dtype probe + convert ----------------
__global__ void probe_kernel(const void* ei) {
    const int* w = (const int*)ei;
    int t = threadIdx.x;            // 256
    int nz = 0;
    for (int i = t; i < 1024; i += 256) nz |= w[2 * i + 1];
    __shared__ int s;
    if (t == 0) s = 0;
    __syncthreads();
    if (nz) atomicOr(&s, 1);
    __syncthreads();
    if (t == 0) d_is64 = (s == 0);  // all-zero odd words => int64
}
__global__ void convert_kernel(const void* ei) {
    int e = blockIdx.x * 256 + threadIdx.x;  // 512x256
    int s, d;
    if (d_is64) {
        const long long* p = (const long long*)ei;
        s = (int)p[e]; d = (int)p[EED + e];
    } else {
        const int* p = (const int*)ei;
        s = p[e]; d = p[EED + e];
    }
    d_esrc[e] = s; d_edst[e] = d;
}

// ---------------- instance-norm stats over (W,C) : rows = b*64+h ----------------
__global__ void stats_kernel(const float* in, int slot) {
    if (in == nullptr) in = (slot == 1) ? d_x1 : d_x2;
    int row = blockIdx.x;            // 256
    const float* p = in + row * 2048;
    int t = threadIdx.x;             // 256
    float s = 0.f, s2 = 0.f;
#pragma unroll
    for (int i = 0; i < 8; i++) { float v = p[t + i * 256]; s += v; s2 += v * v; }
    __shared__ float sh1[256], sh2[256];
    sh1[t] = s; sh2[t] = s2; __syncthreads();
    for (int o = 128; o > 0; o >>= 1) {
        if (t < o) { sh1[t] += sh1[t + o]; sh2[t] += sh2[t + o]; }
        __syncthreads();
    }
    if (t == 0) {
        float m = sh1[0] * (1.0f / 2048.0f);
        float var = sh2[0] * (1.0f / 2048.0f) - m * m;
        d_stats[slot * 512 + row] = m;
        d_stats[slot * 512 + 256 + row] = rsqrtf(var + 1e-5f);
    }
}

__global__ void norm_kernel(const float* nodes) {
    int i = blockIdx.x * 1024 + threadIdx.x;   // 512x1024
    int row = i >> 11;
    d_xn[i] = (nodes[i] - d_stats[row]) * d_stats[256 + row];
}

// ---------------- forward DFT over W (ky 0..15) ----------------
__global__ void fwdW_kernel() {
    int bh = blockIdx.x;            // 256
    int t = threadIdx.x;            // 256
    __shared__ float  xs[2048];
    __shared__ float2 tw[1024];
    for (int i = t; i < 2048; i += 256) xs[i] = d_xn[bh * 2048 + i];
    for (int i = t; i < 1024; i += 256) {
        int ky = i >> 6, w = i & 63; float s, c;
        sincospif(-(float)(ky * w) * (1.0f / 32.0f), &s, &c);
        tw[i] = make_float2(c, s);
    }
    __syncthreads();
#pragma unroll
    for (int r = 0; r < 2; r++) {
        int oi = t + r * 256; int ky = oi >> 5, c = oi & 31;
        float re = 0.f, im = 0.f;
#pragma unroll 8
        for (int w = 0; w < 64; w++) {
            float xv = xs[w * 32 + c]; float2 tv = tw[ky * 64 + w];
            re += xv * tv.x; im += xv * tv.y;
        }
        d_T[(bh * 16 + ky) * 32 + c] = make_float2(re, im);
    }
}

// ---------------- forward DFT over H (kx 0..15, 48..63), *1/64 ----------------
__global__ void fwdH_kernel() {
    int b = blockIdx.x >> 5, kxi = blockIdx.x & 31;   // 128 blocks
    int kx = (kxi < 16) ? kxi : kxi + 32;
    int t = threadIdx.x;                               // 512
    __shared__ float2 tw[64];
    if (t < 64) { float s, c; sincospif(-(float)(kx * t) * (1.0f / 32.0f), &s, &c); tw[t] = make_float2(c, s); }
    __syncthreads();
    int ky = t >> 5, c = t & 31;
    float re = 0.f, im = 0.f;
#pragma unroll 4
    for (int h = 0; h < 64; h++) {
        float2 v = d_T[((b * 64 + h) * 16 + ky) * 32 + c];
        float2 w = tw[h];
        re += v.x * w.x - v.y * w.y;
        im += v.x * w.y + v.y * w.x;
    }
    d_Xft[((b * 32 + kxi) * 16 + ky) * 32 + c] = make_float2(re * (1.0f / 64.0f), im * (1.0f / 64.0f));
}

// ---------------- complex channel mix per (kx,ky) ----------------
__global__ void modemix_kernel(const float* w1re, const float* w1im,
                               const float* w2re, const float* w2im) {
    int kxi = blockIdx.x >> 4, ky = blockIdx.x & 15;   // 512 blocks
    int xm = (kxi < 16) ? kxi : kxi - 16;
    const float* wre = (kxi < 16) ? w1re : w2re;
    const float* wim = (kxi < 16) ? w1im : w2im;
    int t = threadIdx.x;                                // 128
    __shared__ float wr[1024], wi[1024];
    __shared__ float2 Xs[128];
    for (int i = t; i < 1024; i += 128) {
        int off = i * 256 + xm * 16 + ky;   // (ci*32+o)*256 = ci*8192 + o*256
        wr[i] = wre[off]; wi[i] = wim[off];
    }
    { int b = t >> 5, c = t & 31; Xs[t] = d_Xft[((b * 32 + kxi) * 16 + ky) * 32 + c]; }
    __syncthreads();
    int b = t >> 5, o = t & 31;
    float re = 0.f, im = 0.f;
#pragma unroll
    for (int i = 0; i < 32; i++) {
        float2 xv = Xs[b * 32 + i];
        float wrv = wr[i * 32 + o], wiv = wi[i * 32 + o];
        re += xv.x * wrv - xv.y * wiv;
        im += xv.x * wiv + xv.y * wrv;
    }
    d_oft[((b * 32 + kxi) * 16 + ky) * 32 + o] = make_float2(re, im);
}

// ---------------- inverse DFT over H, *1/8 ----------------
__global__ void invH_kernel() {
    int b = blockIdx.x >> 6, h = blockIdx.x & 63;   // 256 blocks
    int t = threadIdx.x;                             // 512
    __shared__ float2 tw[32];
    if (t < 32) {
        int kx = (t < 16) ? t : t + 32; float s, c;
        sincospif((float)(kx * h) * (1.0f / 32.0f), &s, &c);
        tw[t] = make_float2(c, s);
    }
    __syncthreads();
    int ky = t >> 5, o = t & 31;
    float re = 0.f, im = 0.f;
#pragma unroll 4
    for (int k = 0; k < 32; k++) {
        float2 v = d_oft[((b * 32 + k) * 16 + ky) * 32 + o];
        float2 w = tw[k];
        re += v.x * w.x - v.y * w.y;
        im += v.x * w.y + v.y * w.x;
    }
    d_V[((b * 64 + h) * 16 + ky) * 32 + o] = make_float2(re * 0.125f, im * 0.125f);
}

// ---------------- inverse C2R over W, *1/8 ----------------
__global__ void invW_kernel() {
    int bh = blockIdx.x; int t = threadIdx.x;   // 256 x 256
    __shared__ float2 Vs[512];
    __shared__ float2 tw[1024];
    for (int i = t; i < 512; i += 256) Vs[i] = d_V[bh * 512 + i];
    for (int i = t; i < 1024; i += 256) {
        int ky = i >> 6, w = i & 63; float s, c;
        sincospif((float)(ky * w) * (1.0f / 32.0f), &s, &c);
        tw[i] = make_float2(c, s);
    }
    __syncthreads();
#pragma unroll
    for (int r = 0; r < 8; r++) {
        int oi = t + r * 256; int w = oi >> 5, o = oi & 31;
        float acc = 0.f;
#pragma unroll
        for (int ky = 0; ky < 16; ky++) {
            float2 v = Vs[ky * 32 + o]; float2 tv = tw[ky * 64 + w];
            float term = v.x * tv.x - v.y * tv.y;
            acc += (ky == 0) ? term : 2.0f * term;
        }
        d_x1[bh * 2048 + oi] = acc * 0.125f;
    }
}

// ---------------- pointwise MLP 32->64(gelu)->32 ----------------
__global__ void __launch_bounds__(128) mlp_kernel(int which, const float* w1, const float* b1,
                                                  const float* w2, const float* b2) {
    const float* in = (which == 0) ? d_x1 : d_xn;
    float* out = (which == 0) ? d_x1b : d_x2;
    int t = threadIdx.x;   // 128
    __shared__ float w1s[2048], w2s[2048], b1s[64], b2s[32];
    for (int i = t; i < 2048; i += 128) { w1s[i] = w1[i]; w2s[i] = w2[i]; }
    if (t < 64) b1s[t] = b1[t];
    if (t < 32) b2s[t] = b2[t];
    __syncthreads();
    int p = blockIdx.x * 128 + t;   // grid 128
    float m = 0.0f, rs = 1.0f;
    if (which == 0) { int row = p >> 6; m = d_stats[512 + row]; rs = d_stats[512 + 256 + row]; }
    float x[32];
#pragma unroll
    for (int c = 0; c < 32; c++) x[c] = (in[p * 32 + c] - m) * rs;
    float o[32];
#pragma unroll
    for (int j = 0; j < 32; j++) o[j] = b2s[j];
    for (int k = 0; k < 64; k++) {
        float a = b1s[k];
#pragma unroll
        for (int c = 0; c < 32; c++) a += x[c] * w1s[c * 64 + k];
        a = gelu_f(a);
#pragma unroll
        for (int j = 0; j < 32; j++) o[j] += a * w2s[k * 32 + j];
    }
#pragma unroll
    for (int j = 0; j < 32; j++) out[p * 32 + j] = o[j];
}

// ---------------- edge hidden h = gelu(attr @ kw1 + kb1) ----------------
__global__ void edgehid_kernel(const float* attr, const float* w1, const float* b1) {
    int e0 = blockIdx.x * 64;   // 2048 blocks
    int t = threadIdx.x;        // 256
    __shared__ float at[384], w1s[384], b1s[64];
    for (int i = t; i < 384; i += 256) { at[i] = attr[e0 * 6 + i]; w1s[i] = w1[i]; }
    if (t < 64) b1s[t] = b1[t];
    __syncthreads();
#pragma unroll
    for (int r = 0; r < 16; r++) {
        int i = t + r * 256; int el = i >> 6, k = i & 63;
        float a = b1s[k];
#pragma unroll
        for (int d = 0; d < 6; d++) a += at[el * 6 + d] * w1s[d * 64 + k];
        d_h[(long long)(e0 + el) * 64 + k] = gelu_f(a);
    }
}

// ---------------- g GEMM: [16384,32] @ [32,2048] ----------------
__global__ void gemm_g_kernel(const float* __restrict__ w2) {
    __shared__ float As[64 * 33];
    __shared__ float Bs[32 * 65];
    int row0 = blockIdx.x * 64;     // grid (256,32)
    int col0 = blockIdx.y * 64;
    int t = threadIdx.x;            // 256
    for (int i = t; i < 2048; i += 256)
        As[(i >> 5) * 33 + (i & 31)] = d_xn[(row0 + (i >> 5)) * 32 + (i & 31)];
    for (int i = t; i < 2048; i += 256) {
        int c = i >> 6, j = i & 63; int col = col0 + j;
        Bs[c * 65 + j] = w2[(col >> 5) * 1024 + c * 32 + (col & 31)];
    }
    __syncthreads();
    int tr = (t >> 4) * 4, tc = (t & 15) * 4;
    float acc[4][4] = {};
#pragma unroll
    for (int c = 0; c < 32; c++) {
        float a0 = As[tr * 33 + c], a1 = As[(tr + 1) * 33 + c],
              a2 = As[(tr + 2) * 33 + c], a3 = As[(tr + 3) * 33 + c];
        float b0 = Bs[c * 65 + tc], b1 = Bs[c * 65 + tc + 1],
              b2 = Bs[c * 65 + tc + 2], b3 = Bs[c * 65 + tc + 3];
        acc[0][0] += a0 * b0; acc[0][1] += a0 * b1; acc[0][2] += a0 * b2; acc[0][3] += a0 * b3;
        acc[1][0] += a1 * b0; acc[1][1] += a1 * b1; acc[1][2] += a1 * b2; acc[1][3] += a1 * b3;
        acc[2][0] += a2 * b0; acc[2][1] += a2 * b1; acc[2][2] += a2 * b2; acc[2][3] += a2 * b3;
        acc[3][0] += a3 * b0; acc[3][1] += a3 * b1; acc[3][2] += a3 * b2; acc[3][3] += a3 * b3;
    }
#pragma unroll
    for (int i = 0; i < 4; i++)
#pragma unroll
        for (int j = 0; j < 4; j++)
            d_g[(long long)(row0 + tr + i) * 2048 + col0 + tc + j] = acc[i][j];
}

// ---------------- CSR build ----------------
__global__ void zero_kernel() {
    int i = blockIdx.x * 1024 + threadIdx.x;   // 8x1024
    d_cnt[i] = 0; d_cur[i] = 0;
}
__global__ void hist_kernel() {
    int e = blockIdx.x * 256 + threadIdx.x;    // 512x256
    atomicAdd(&d_cnt[d_esrc[e]], 1);
    atomicAdd(&d_cnt[NND + d_edst[e]], 1);
}
__global__ void scan_kernel() {
    int a = blockIdx.x;   // 0=src, 1=dst
    int t = threadIdx.x;  // 1024
    const int* cnt = d_cnt + a * NND;
    int* off = d_offA + a * (NND + 1);
    int v0 = cnt[t * 4], v1 = cnt[t * 4 + 1], v2 = cnt[t * 4 + 2], v3 = cnt[t * 4 + 3];
    int s = v0 + v1 + v2 + v3;
    __shared__ int sh[1024];
    sh[t] = s; __syncthreads();
    for (int o1 = 1; o1 < 1024; o1 <<= 1) {
        int v = (t >= o1) ? sh[t - o1] : 0;
        __syncthreads();
        sh[t] += v;
        __syncthreads();
    }
    int excl = sh[t] - s;
    off[t * 4] = excl; off[t * 4 + 1] = excl + v0;
    off[t * 4 + 2] = excl + v0 + v1; off[t * 4 + 3] = excl + v0 + v1 + v2;
    if (t == 1023) off[NND] = sh[1023];
}
__global__ void fill_kernel() {
    int e = blockIdx.x * 256 + threadIdx.x;    // 512x256
    int s = d_esrc[e], d2 = d_edst[e];
    int p = atomicAdd(&d_cur[s], 1);
    d_eid[d_offA[s] + p] = e;
    int q = atomicAdd(&d_cur[NND + d2], 1);
    d_eid[EED + d_offA[(NND + 1) + d2] + q] = e;
}

// ---------------- per-src msg kernel ----------------
__global__ void __launch_bounds__(128) edgemsg_kernel(const float* __restrict__ kb2) {
    int node = blockIdx.x;   // 4096
    int t = threadIdx.x; int b = t >> 5, o = t & 31;
    int s0 = d_offA[node], s1 = d_offA[node + 1];
    if (s0 == s1) return;
    __shared__ float gs[8192];    // [b][k*32+o]
    __shared__ float xsrc[128];
    __shared__ float hs[512];
    __shared__ int es[8];
    for (int i = t; i < 8192; i += 128)
        gs[i] = d_g[(long long)((i >> 11) * NND + node) * 2048 + (i & 2047)];
    xsrc[t] = d_xn[(b * NND + node) * 32 + o];
    __syncthreads();
    float xb = 0.f;
#pragma unroll
    for (int c = 0; c < 32; c++) xb += xsrc[b * 32 + c] * kb2[c * 32 + o];
    for (int ec = s0; ec < s1; ec += 8) {
        int nch = min(8, s1 - ec);
        if (t < nch) es[t] = d_eid[ec + t];
        __syncthreads();
        for (int i = t; i < nch * 64; i += 128)
            hs[i] = d_h[(long long)es[i >> 6] * 64 + (i & 63)];
        __syncthreads();
        float acc[8];
#pragma unroll
        for (int j = 0; j < 8; j++) acc[j] = xb;
        for (int k = 0; k < 64; k++) {
            float gv = gs[b * 2048 + k * 32 + o];
#pragma unroll
            for (int j = 0; j < 8; j++) acc[j] += hs[j * 64 + k] * gv;
        }
        for (int j = 0; j < nch; j++)
            d_msg[((long long)es[j] * 4 + b) * 32 + o] = acc[j];
        __syncthreads();
    }
}

// ---------------- dst gather + root + bias + combine + gelu ----------------
__global__ void __launch_bounds__(128) final_kernel(const float* __restrict__ root,
                                                    const float* __restrict__ gbias,
                                                    float* __restrict__ out) {
    int n = blockIdx.x;   // 4096
    int t = threadIdx.x; int b = t >> 5, o = t & 31;
    __shared__ float roots[1024];
    __shared__ float xs[128];
    for (int i = t; i < 1024; i += 128) roots[i] = root[i];
    xs[t] = d_xn[(b * NND + n) * 32 + o];
    __syncthreads();
    float acc = gbias[o];
#pragma unroll
    for (int c = 0; c < 32; c++) acc += xs[b * 32 + c] * roots[c * 32 + o];
    int s0 = d_offA[(NND + 1) + n], s1 = d_offA[(NND + 1) + n + 1];
    for (int i = s0; i < s1; i++) {
        int e = d_eid[EED + i];
        acc += d_msg[((long long)e * 4 + b) * 32 + o];
    }
    int p = b * NND + n; int row = p >> 6;
    float x2v = (d_x2[(long long)p * 32 + o] - d_stats[1024 + row]) * d_stats[1024 + 256 + row];
    float s = d_x1b[(long long)p * 32 + o] + x2v + acc;
    out[(long long)p * 32 + o] = gelu_f(s);
}

// ---------------- launch ----------------
extern "C" void kernel_launch(void* const* d_in, const int* in_sizes, int n_in,
                              void* d_out, int out_size) {
    const float* nodes  = (const float*)d_in[0];
    const void*  eidx   = d_in[1];
    const float* eattr  = (const float*)d_in[2];
    const float* w1re   = (const float*)d_in[3];
    const float* w1im   = (const float*)d_in[4];
    const float* w2re   = (const float*)d_in[5];
    const float* w2im   = (const float*)d_in[6];
    const float* mlp_w1 = (const float*)d_in[7];
    const float* mlp_b1 = (const float*)d_in[8];
    const float* mlp_w2 = (const float*)d_in[9];
    const float* mlp_b2 = (const float*)d_in[10];
    const float* wm_w1  = (const float*)d_in[11];
    const float* wm_b1  = (const float*)d_in[12];
    const float* wm_w2  = (const float*)d_in[13];
    const float* wm_b2  = (const float*)d_in[14];
    const float* kw1    = (const float*)d_in[15];
    const float* kb1    = (const float*)d_in[16];
    const float* kw2    = (const float*)d_in[17];
    const float* kb2    = (const float*)d_in[18];
    const float* root   = (const float*)d_in[19];
    const float* gbias  = (const float*)d_in[20];
    float* out = (float*)d_out;

    // edge index handling + CSR build (independent of x pipeline)
    probe_kernel<<<1, 256>>>(eidx);
    convert_kernel<<<512, 256>>>(eidx);
    zero_kernel<<<8, 1024>>>();
    hist_kernel<<<512, 256>>>();
    scan_kernel<<<2, 1024>>>();
    fill_kernel<<<512, 256>>>();

    // normalize input
    stats_kernel<<<256, 256>>>(nodes, 0);
    norm_kernel<<<512, 1024>>>(nodes);

    // spectral branch
    fwdW_kernel<<<256, 256>>>();
    fwdH_kernel<<<128, 512>>>();
    modemix_kernel<<<512, 128>>>(w1re, w1im, w2re, w2im);
    invH_kernel<<<256, 512>>>();
    invW_kernel<<<256, 256>>>();
    stats_kernel<<<256, 256>>>(nullptr, 1);
    mlp_kernel<<<128, 128>>>(0, mlp_w1, mlp_b1, mlp_w2, mlp_b2);

    // pointwise branch (x2 pre-norm; normalized in final_kernel)
    mlp_kernel<<<128, 128>>>(1, wm_w1, wm_b1, wm_w2, wm_b2);
    stats_kernel<<<256, 256>>>(nullptr, 2);

    // GNO branch
    edgehid_kernel<<<2048, 256>>>(eattr, kw1, kb1);
    {
        dim3 g(256, 32);
        gemm_g_kernel<<<g, 256>>>(kw2);
    }
    edgemsg_kernel<<<4096, 128>>>(kb2);

    // combine
    final_kernel<<<4096, 128>>>(root, gbias, out);
}

// round 6
// speedup vs baseline: 1.1520x; 1.1520x over previous
#include <cuda_runtime.h>
#include <cuda_fp16.h>
#include <math.h>

#define BB 4
#define NND 4096
#define EED 131072

// ---------------- scratch ----------------
__device__ float  d_stats[3 * 512];
__device__ float  d_xn  [BB * NND * 32];
__device__ float2 d_T   [BB * 64 * 16 * 32];
__device__ float2 d_Xft [BB * 32 * 16 * 32];
__device__ float2 d_oft [BB * 32 * 16 * 32];
__device__ float2 d_V   [BB * 64 * 16 * 32];
__device__ float  d_x1  [BB * NND * 32];
__device__ float  d_x1b [BB * NND * 32];
__device__ float  d_x2  [BB * NND * 32];
__device__ __half d_hh  [(long long)EED * 64];
__device__ __half d_gh  [(long long)BB * NND * 64 * 32];
__device__ float  d_msg [(long long)EED * BB * 32];
__device__ int    d_esrc[EED];
__device__ int    d_edst[EED];
__device__ int    d_is64;
__device__ int    d_cnt [2 * NND];
__device__ int    d_offA[2 * (NND + 1)];
__device__ int    d_cur [2 * NND];
__device__ int    d_eid [2 * EED];

__device__ __forceinline__ float gelu_f(float x) {
    return 0.5f * x * (1.0f + erff(x * 0.70710678118654752f));
}
__device__ __forceinline__ unsigned long long pack2(float lo, float hi) {
    unsigned long long r;
    asm("mov.b64 %0, {%1,%2};" : "=l"(r) : "f"(lo), "f"(hi));
    return r;
}
__device__ __forceinline__ void unpack2(unsigned long long v, float& lo, float& hi) {
    asm("mov.b64 {%0,%1}, %2;" : "=f"(lo), "=f"(hi) : "l"(v));
}
__device__ __forceinline__ void fma2(unsigned long long& a, unsigned long long x, unsigned long long y) {
    asm("fma.rn.f32x2 %0, %1, %2, %0;" : "+l"(a) : "l"(x), "l"(y));
}

// ---------------- init: zero cnt/cur + probe edge dtype ----------------
__global__ void initcsr_kernel(const void* ei) {
    int i = blockIdx.x * 1024 + threadIdx.x;   // 8x1024
    d_cnt[i] = 0; d_cur[i] = 0;
    if (blockIdx.x == 0 && threadIdx.x < 256) {
        const int* w = (const int*)ei;
        int t = threadIdx.x;
        int nz = 0;
        for (int k = t; k < 1024; k += 256) nz |= w[2 * k + 1];
        __shared__ int s;
        if (t == 0) s = 0;
        __syncthreads();
        if (nz) atomicOr(&s, 1);
        __syncthreads();
        if (t == 0) d_is64 = (s == 0);   // all-zero odd words => int64
    }
}

// ---------------- convert + histogram ----------------
__global__ void convhist_kernel(const void* ei) {
    int e = blockIdx.x * 256 + threadIdx.x;  // 512x256
    int s, d;
    if (d_is64) {
        const long long* p = (const long long*)ei;
        s = (int)p[e]; d = (int)p[EED + e];
    } else {
        const int* p = (const int*)ei;
        s = p[e]; d = p[EED + e];
    }
    d_esrc[e] = s; d_edst[e] = d;
    atomicAdd(&d_cnt[s], 1);
    atomicAdd(&d_cnt[NND + d], 1);
}

__global__ void scan_kernel() {
    int a = blockIdx.x;   // 0=src, 1=dst
    int t = threadIdx.x;  // 1024
    const int* cnt = d_cnt + a * NND;
    int* off = d_offA + a * (NND + 1);
    int v0 = cnt[t * 4], v1 = cnt[t * 4 + 1], v2 = cnt[t * 4 + 2], v3 = cnt[t * 4 + 3];
    int s = v0 + v1 + v2 + v3;
    __shared__ int sh[1024];
    sh[t] = s; __syncthreads();
    for (int o1 = 1; o1 < 1024; o1 <<= 1) {
        int v = (t >= o1) ? sh[t - o1] : 0;
        __syncthreads();
        sh[t] += v;
        __syncthreads();
    }
    int excl = sh[t] - s;
    off[t * 4] = excl; off[t * 4 + 1] = excl + v0;
    off[t * 4 + 2] = excl + v0 + v1; off[t * 4 + 3] = excl + v0 + v1 + v2;
    if (t == 1023) off[NND] = sh[1023];
}

__global__ void fill_kernel() {
    int e = blockIdx.x * 256 + threadIdx.x;    // 512x256
    int s = d_esrc[e], d2 = d_edst[e];
    int p = atomicAdd(&d_cur[s], 1);
    d_eid[d_offA[s] + p] = e;
    int q = atomicAdd(&d_cur[NND + d2], 1);
    d_eid[EED + d_offA[(NND + 1) + d2] + q] = e;
}

// ---------------- instance-norm stats over (W,C) ----------------
__global__ void stats_kernel(const float* in, int slot) {
    int row = blockIdx.x;            // 256
    const float* p = in + row * 2048;
    int t = threadIdx.x;             // 256
    float s = 0.f, s2 = 0.f;
#pragma unroll
    for (int i = 0; i < 8; i++) { float v = p[t + i * 256]; s += v; s2 += v * v; }
    __shared__ float sh1[256], sh2[256];
    sh1[t] = s; sh2[t] = s2; __syncthreads();
    for (int o = 128; o > 0; o >>= 1) {
        if (t < o) { sh1[t] += sh1[t + o]; sh2[t] += sh2[t + o]; }
        __syncthreads();
    }
    if (t == 0) {
        float m = sh1[0] * (1.0f / 2048.0f);
        float var = sh2[0] * (1.0f / 2048.0f) - m * m;
        d_stats[slot * 512 + row] = m;
        d_stats[slot * 512 + 256 + row] = rsqrtf(var + 1e-5f);
    }
}

__global__ void norm_kernel(const float* nodes) {
    int i = blockIdx.x * 1024 + threadIdx.x;   // 512x1024
    int row = i >> 11;
    d_xn[i] = (nodes[i] - d_stats[row]) * d_stats[256 + row];
}

// ---------------- forward DFT over W (ky 0..15) ----------------
__global__ void fwdW_kernel() {
    int bh = blockIdx.x;            // 256
    int t = threadIdx.x;            // 256
    __shared__ float  xs[2048];
    __shared__ float2 tw[1024];
    for (int i = t; i < 2048; i += 256) xs[i] = d_xn[bh * 2048 + i];
    for (int i = t; i < 1024; i += 256) {
        int ky = i >> 6, w = i & 63; float s, c;
        sincospif(-(float)(ky * w) * (1.0f / 32.0f), &s, &c);
        tw[i] = make_float2(c, s);
    }
    __syncthreads();
#pragma unroll
    for (int r = 0; r < 2; r++) {
        int oi = t + r * 256; int ky = oi >> 5, c = oi & 31;
        float re = 0.f, im = 0.f;
#pragma unroll 8
        for (int w = 0; w < 64; w++) {
            float xv = xs[w * 32 + c]; float2 tv = tw[ky * 64 + w];
            re += xv * tv.x; im += xv * tv.y;
        }
        d_T[(bh * 16 + ky) * 32 + c] = make_float2(re, im);
    }
}

// ---------------- forward DFT over H (kx 0..15, 48..63), *1/64 ----------------
__global__ void fwdH_kernel() {
    int b = blockIdx.x >> 5, kxi = blockIdx.x & 31;   // 128 blocks
    int kx = (kxi < 16) ? kxi : kxi + 32;
    int t = threadIdx.x;                               // 512
    __shared__ float2 tw[64];
    if (t < 64) { float s, c; sincospif(-(float)(kx * t) * (1.0f / 32.0f), &s, &c); tw[t] = make_float2(c, s); }
    __syncthreads();
    int ky = t >> 5, c = t & 31;
    float re = 0.f, im = 0.f;
#pragma unroll 4
    for (int h = 0; h < 64; h++) {
        float2 v = d_T[((b * 64 + h) * 16 + ky) * 32 + c];
        float2 w = tw[h];
        re += v.x * w.x - v.y * w.y;
        im += v.x * w.y + v.y * w.x;
    }
    d_Xft[((b * 32 + kxi) * 16 + ky) * 32 + c] = make_float2(re * (1.0f / 64.0f), im * (1.0f / 64.0f));
}

// ---------------- complex channel mix per (kx,ky) ----------------
__global__ void modemix_kernel(const float* w1re, const float* w1im,
                               const float* w2re, const float* w2im) {
    int kxi = blockIdx.x >> 4, ky = blockIdx.x & 15;   // 512 blocks
    int xm = (kxi < 16) ? kxi : kxi - 16;
    const float* wre = (kxi < 16) ? w1re : w2re;
    const float* wim = (kxi < 16) ? w1im : w2im;
    int t = threadIdx.x;                                // 128
    __shared__ float wr[1024], wi[1024];
    __shared__ float2 Xs[128];
    for (int i = t; i < 1024; i += 128) {
        int off = i * 256 + xm * 16 + ky;
        wr[i] = wre[off]; wi[i] = wim[off];
    }
    { int b = t >> 5, c = t & 31; Xs[t] = d_Xft[((b * 32 + kxi) * 16 + ky) * 32 + c]; }
    __syncthreads();
    int b = t >> 5, o = t & 31;
    float re = 0.f, im = 0.f;
#pragma unroll
    for (int i = 0; i < 32; i++) {
        float2 xv = Xs[b * 32 + i];
        float wrv = wr[i * 32 + o], wiv = wi[i * 32 + o];
        re += xv.x * wrv - xv.y * wiv;
        im += xv.x * wiv + xv.y * wrv;
    }
    d_oft[((b * 32 + kxi) * 16 + ky) * 32 + o] = make_float2(re, im);
}

// ---------------- inverse DFT over H, *1/8 ----------------
__global__ void invH_kernel() {
    int b = blockIdx.x >> 6, h = blockIdx.x & 63;   // 256 blocks
    int t = threadIdx.x;                             // 512
    __shared__ float2 tw[32];
    if (t < 32) {
        int kx = (t < 16) ? t : t + 32; float s, c;
        sincospif((float)(kx * h) * (1.0f / 32.0f), &s, &c);
        tw[t] = make_float2(c, s);
    }
    __syncthreads();
    int ky = t >> 5, o = t & 31;
    float re = 0.f, im = 0.f;
#pragma unroll 4
    for (int k = 0; k < 32; k++) {
        float2 v = d_oft[((b * 32 + k) * 16 + ky) * 32 + o];
        float2 w = tw[k];
        re += v.x * w.x - v.y * w.y;
        im += v.x * w.y + v.y * w.x;
    }
    d_V[((b * 64 + h) * 16 + ky) * 32 + o] = make_float2(re * 0.125f, im * 0.125f);
}

// ---------------- inverse C2R over W, *1/8, fused stats(slot1) ----------------
__global__ void invW_kernel() {
    int bh = blockIdx.x; int t = threadIdx.x;   // 256 x 256
    __shared__ float2 Vs[512];
    __shared__ float2 tw[1024];
    __shared__ float sh1[256], sh2[256];
    for (int i = t; i < 512; i += 256) Vs[i] = d_V[bh * 512 + i];
    for (int i = t; i < 1024; i += 256) {
        int ky = i >> 6, w = i & 63; float s, c;
        sincospif((float)(ky * w) * (1.0f / 32.0f), &s, &c);
        tw[i] = make_float2(c, s);
    }
    __syncthreads();
    float ss = 0.f, ss2 = 0.f;
#pragma unroll
    for (int r = 0; r < 8; r++) {
        int oi = t + r * 256; int w = oi >> 5, o = oi & 31;
        float acc = 0.f;
#pragma unroll
        for (int ky = 0; ky < 16; ky++) {
            float2 v = Vs[ky * 32 + o]; float2 tv = tw[ky * 64 + w];
            float term = v.x * tv.x - v.y * tv.y;
            acc += (ky == 0) ? term : 2.0f * term;
        }
        acc *= 0.125f;
        d_x1[bh * 2048 + oi] = acc;
        ss += acc; ss2 += acc * acc;
    }
    sh1[t] = ss; sh2[t] = ss2; __syncthreads();
    for (int o = 128; o > 0; o >>= 1) {
        if (t < o) { sh1[t] += sh1[t + o]; sh2[t] += sh2[t + o]; }
        __syncthreads();
    }
    if (t == 0) {
        float m = sh1[0] * (1.0f / 2048.0f);
        float var = sh2[0] * (1.0f / 2048.0f) - m * m;
        d_stats[512 + bh] = m;
        d_stats[512 + 256 + bh] = rsqrtf(var + 1e-5f);
    }
}

// ---------------- MLP on inorm(x1) -> d_x1b ----------------
__global__ void __launch_bounds__(128) mlp0_kernel(const float* w1, const float* b1,
                                                   const float* w2, const float* b2) {
    int t = threadIdx.x;   // 128
    __shared__ float w1s[2048], w2s[2048], b1s[64], b2s[32];
    for (int i = t; i < 2048; i += 128) { w1s[i] = w1[i]; w2s[i] = w2[i]; }
    if (t < 64) b1s[t] = b1[t];
    if (t < 32) b2s[t] = b2[t];
    __syncthreads();
    int p = blockIdx.x * 128 + t;   // grid 128
    int row = p >> 6;
    float m = d_stats[512 + row], rs = d_stats[512 + 256 + row];
    float x[32];
#pragma unroll
    for (int c = 0; c < 32; c++) x[c] = (d_x1[p * 32 + c] - m) * rs;
    float o[32];
#pragma unroll
    for (int j = 0; j < 32; j++) o[j] = b2s[j];
    for (int k = 0; k < 64; k++) {
        float a = b1s[k];
#pragma unroll
        for (int c = 0; c < 32; c++) a += x[c] * w1s[c * 64 + k];
        a = gelu_f(a);
#pragma unroll
        for (int j = 0; j < 32; j++) o[j] += a * w2s[k * 32 + j];
    }
#pragma unroll
    for (int j = 0; j < 32; j++) d_x1b[p * 32 + j] = o[j];
}

// ---------------- MLP on xn -> d_x2, fused stats(slot2) ----------------
__global__ void __launch_bounds__(128) mlp1_kernel(const float* w1, const float* b1,
                                                   const float* w2, const float* b2) {
    int t = threadIdx.x;   // 128
    __shared__ float w1s[2048], w2s[2048], b1s[64], b2s[32];
    __shared__ float sh1[128], sh2[128];
    for (int i = t; i < 2048; i += 128) { w1s[i] = w1[i]; w2s[i] = w2[i]; }
    if (t < 64) b1s[t] = b1[t];
    if (t < 32) b2s[t] = b2[t];
    __syncthreads();
    int p = blockIdx.x * 128 + t;   // grid 128; block covers rows 2*blk, 2*blk+1
    float x[32];
#pragma unroll
    for (int c = 0; c < 32; c++) x[c] = d_xn[p * 32 + c];
    float o[32];
#pragma unroll
    for (int j = 0; j < 32; j++) o[j] = b2s[j];
    for (int k = 0; k < 64; k++) {
        float a = b1s[k];
#pragma unroll
        for (int c = 0; c < 32; c++) a += x[c] * w1s[c * 64 + k];
        a = gelu_f(a);
#pragma unroll
        for (int j = 0; j < 32; j++) o[j] += a * w2s[k * 32 + j];
    }
    float ss = 0.f, ss2 = 0.f;
#pragma unroll
    for (int j = 0; j < 32; j++) {
        d_x2[p * 32 + j] = o[j];
        ss += o[j]; ss2 += o[j] * o[j];
    }
    sh1[t] = ss; sh2[t] = ss2; __syncthreads();
    int half = t & 64;        // 0 or 64: which row of the block
    int l = t & 63;
    for (int off = 32; off > 0; off >>= 1) {
        if (l < off) { sh1[half + l] += sh1[half + l + off]; sh2[half + l] += sh2[half + l + off]; }
        __syncthreads();
    }
    if (l == 0) {
        int row = blockIdx.x * 2 + (half >> 6);
        float m = sh1[half] * (1.0f / 2048.0f);
        float var = sh2[half] * (1.0f / 2048.0f) - m * m;
        d_stats[1024 + row] = m;
        d_stats[1024 + 256 + row] = rsqrtf(var + 1e-5f);
    }
}

// ---------------- edge hidden h = gelu(attr @ kw1 + kb1), fp16 out ----------------
__global__ void edgehid_kernel(const float* attr, const float* w1, const float* b1) {
    int e0 = blockIdx.x * 64;   // 2048 blocks
    int t = threadIdx.x;        // 256
    __shared__ float at[384], w1s[384], b1s[64];
    for (int i = t; i < 384; i += 256) { at[i] = attr[e0 * 6 + i]; w1s[i] = w1[i]; }
    if (t < 64) b1s[t] = b1[t];
    __syncthreads();
#pragma unroll
    for (int r = 0; r < 16; r++) {
        int i = t + r * 256; int el = i >> 6, k = i & 63;
        float a = b1s[k];
#pragma unroll
        for (int d = 0; d < 6; d++) a += at[el * 6 + d] * w1s[d * 64 + k];
        d_hh[(long long)(e0 + el) * 64 + k] = __float2half_rn(gelu_f(a));
    }
}

// ---------------- g GEMM: [16384,32] @ [32,2048], fp16 out ----------------
__global__ void gemm_g_kernel(const float* __restrict__ w2) {
    __shared__ float As[64 * 33];
    __shared__ float Bs[32 * 65];
    int row0 = blockIdx.x * 64;     // grid (256,32)
    int col0 = blockIdx.y * 64;
    int t = threadIdx.x;            // 256
    for (int i = t; i < 2048; i += 256)
        As[(i >> 5) * 33 + (i & 31)] = d_xn[(row0 + (i >> 5)) * 32 + (i & 31)];
    for (int i = t; i < 2048; i += 256) {
        int c = i >> 6, j = i & 63; int col = col0 + j;
        Bs[c * 65 + j] = w2[(col >> 5) * 1024 + c * 32 + (col & 31)];
    }
    __syncthreads();
    int tr = (t >> 4) * 4, tc = (t & 15) * 4;
    float acc[4][4] = {};
#pragma unroll
    for (int c = 0; c < 32; c++) {
        float a0 = As[tr * 33 + c], a1 = As[(tr + 1) * 33 + c],
              a2 = As[(tr + 2) * 33 + c], a3 = As[(tr + 3) * 33 + c];
        float b0 = Bs[c * 65 + tc], b1 = Bs[c * 65 + tc + 1],
              b2 = Bs[c * 65 + tc + 2], b3 = Bs[c * 65 + tc + 3];
        acc[0][0] += a0 * b0; acc[0][1] += a0 * b1; acc[0][2] += a0 * b2; acc[0][3] += a0 * b3;
        acc[1][0] += a1 * b0; acc[1][1] += a1 * b1; acc[1][2] += a1 * b2; acc[1][3] += a1 * b3;
        acc[2][0] += a2 * b0; acc[2][1] += a2 * b1; acc[2][2] += a2 * b2; acc[2][3] += a2 * b3;
        acc[3][0] += a3 * b0; acc[3][1] += a3 * b1; acc[3][2] += a3 * b2; acc[3][3] += a3 * b3;
    }
    __half2* gh2 = (__half2*)d_gh;
#pragma unroll
    for (int i = 0; i < 4; i++) {
        long long base = (long long)(row0 + tr + i) * 2048 + col0 + tc;
        gh2[base >> 1]       = __floats2half2_rn(acc[i][0], acc[i][1]);
        gh2[(base >> 1) + 1] = __floats2half2_rn(acc[i][2], acc[i][3]);
    }
}

// ---------------- per-src msg: chunk16 + f32x2 FMA ----------------
__global__ void __launch_bounds__(128) edgemsg_kernel(const float* __restrict__ kb2) {
    int node = blockIdx.x;   // 4096
    int t = threadIdx.x; int b = t >> 5, o = t & 31;
    int s0 = d_offA[node], s1 = d_offA[node + 1];
    if (s0 == s1) return;
    __shared__ float gs[8192];       // [b][k*32+o] fp32
    __shared__ float hs[64 * 18];    // [k][j] (16 edges + 2 pad)
    __shared__ float xsrc[128];
    __shared__ int es[16];
    {
        const __half2* gh2 = (const __half2*)d_gh;
        float2* gs2 = (float2*)gs;
        for (int i = t; i < 4096; i += 128) {
            int bb = i >> 10, idx = i & 1023;
            gs2[i] = __half22float2(gh2[(long long)(bb * NND + node) * 1024 + idx]);
        }
    }
    xsrc[t] = d_xn[(b * NND + node) * 32 + o];
    __syncthreads();
    float xb = 0.f;
#pragma unroll
    for (int c = 0; c < 32; c++) xb += xsrc[b * 32 + c] * kb2[c * 32 + o];
    const __half2* hh2 = (const __half2*)d_hh;
    for (int ec = s0; ec < s1; ec += 16) {
        int nch = min(16, s1 - ec);
        __syncthreads();
        if (t < nch) es[t] = d_eid[ec + t];
        __syncthreads();
        for (int i = t; i < nch * 32; i += 128) {
            int j = i >> 5, kp = i & 31;
            float2 hv = __half22float2(hh2[(long long)es[j] * 32 + kp]);
            hs[(2 * kp) * 18 + j] = hv.x;
            hs[(2 * kp + 1) * 18 + j] = hv.y;
        }
        __syncthreads();
        unsigned long long acc2[8];
#pragma unroll
        for (int jp = 0; jp < 8; jp++) acc2[jp] = pack2(xb, xb);
#pragma unroll 4
        for (int k = 0; k < 64; k++) {
            float gv = gs[b * 2048 + k * 32 + o];
            unsigned long long g2 = pack2(gv, gv);
            const unsigned long long* hr = (const unsigned long long*)&hs[k * 18];
#pragma unroll
            for (int jp = 0; jp < 8; jp++) fma2(acc2[jp], hr[jp], g2);
        }
#pragma unroll
        for (int jp = 0; jp < 8; jp++) {
            float lo, hi;
            unpack2(acc2[jp], lo, hi);
            int j = 2 * jp;
            if (j < nch)     d_msg[((long long)es[j] * 4 + b) * 32 + o] = lo;
            if (j + 1 < nch) d_msg[((long long)es[j + 1] * 4 + b) * 32 + o] = hi;
        }
    }
}

// ---------------- dst gather + root + bias + combine + gelu ----------------
__global__ void __launch_bounds__(128) final_kernel(const float* __restrict__ root,
                                                    const float* __restrict__ gbias,
                                                    float* __restrict__ out) {
    int n = blockIdx.x;   // 4096
    int t = threadIdx.x; int b = t >> 5, o = t & 31;
    __shared__ float roots[1024];
    __shared__ float xs[128];
    for (int i = t; i < 1024; i += 128) roots[i] = root[i];
    xs[t] = d_xn[(b * NND + n) * 32 + o];
    __syncthreads();
    float acc = gbias[o];
#pragma unroll
    for (int c = 0; c < 32; c++) acc += xs[b * 32 + c] * roots[c * 32 + o];
    int s0 = d_offA[(NND + 1) + n], s1 = d_offA[(NND + 1) + n + 1];
    int i = s0;
    float a0 = 0.f, a1 = 0.f, a2 = 0.f, a3 = 0.f;
    for (; i + 4 <= s1; i += 4) {
        int e0 = d_eid[EED + i], e1 = d_eid[EED + i + 1];
        int e2 = d_eid[EED + i + 2], e3 = d_eid[EED + i + 3];
        float m0 = d_msg[((long long)e0 * 4 + b) * 32 + o];
        float m1 = d_msg[((long long)e1 * 4 + b) * 32 + o];
        float m2 = d_msg[((long long)e2 * 4 + b) * 32 + o];
        float m3 = d_msg[((long long)e3 * 4 + b) * 32 + o];
        a0 += m0; a1 += m1; a2 += m2; a3 += m3;
    }
    for (; i < s1; i++) {
        int e = d_eid[EED + i];
        a0 += d_msg[((long long)e * 4 + b) * 32 + o];
    }
    acc += (a0 + a1) + (a2 + a3);
    int p = b * NND + n; int row = p >> 6;
    float x2v = (d_x2[(long long)p * 32 + o] - d_stats[1024 + row]) * d_stats[1024 + 256 + row];
    float s = d_x1b[(long long)p * 32 + o] + x2v + acc;
    out[(long long)p * 32 + o] = gelu_f(s);
}

// ---------------- launch ----------------
extern "C" void kernel_launch(void* const* d_in, const int* in_sizes, int n_in,
                              void* d_out, int out_size) {
    const float* nodes  = (const float*)d_in[0];
    const void*  eidx   = d_in[1];
    const float* eattr  = (const float*)d_in[2];
    const float* w1re   = (const float*)d_in[3];
    const float* w1im   = (const float*)d_in[4];
    const float* w2re   = (const float*)d_in[5];
    const float* w2im   = (const float*)d_in[6];
    const float* mlp_w1 = (const float*)d_in[7];
    const float* mlp_b1 = (const float*)d_in[8];
    const float* mlp_w2 = (const float*)d_in[9];
    const float* mlp_b2 = (const float*)d_in[10];
    const float* wm_w1  = (const float*)d_in[11];
    const float* wm_b1  = (const float*)d_in[12];
    const float* wm_w2  = (const float*)d_in[13];
    const float* wm_b2  = (const float*)d_in[14];
    const float* kw1    = (const float*)d_in[15];
    const float* kb1    = (const float*)d_in[16];
    const float* kw2    = (const float*)d_in[17];
    const float* kb2    = (const float*)d_in[18];
    const float* root   = (const float*)d_in[19];
    const float* gbias  = (const float*)d_in[20];
    float* out = (float*)d_out;

    // CSR build
    initcsr_kernel<<<8, 1024>>>(eidx);
    convhist_kernel<<<512, 256>>>(eidx);
    scan_kernel<<<2, 1024>>>();
    fill_kernel<<<512, 256>>>();

    // normalize input
    stats_kernel<<<256, 256>>>(nodes, 0);
    norm_kernel<<<512, 1024>>>(nodes);

    // spectral branch
    fwdW_kernel<<<256, 256>>>();
    fwdH_kernel<<<128, 512>>>();
    modemix_kernel<<<512, 128>>>(w1re, w1im, w2re, w2im);
    invH_kernel<<<256, 512>>>();
    invW_kernel<<<256, 256>>>();          // + stats slot1
    mlp0_kernel<<<128, 128>>>(mlp_w1, mlp_b1, mlp_w2, mlp_b2);

    // pointwise branch
    mlp1_kernel<<<128, 128>>>(wm_w1, wm_b1, wm_w2, wm_b2);   // + stats slot2

    // GNO branch
    edgehid_kernel<<<2048, 256>>>(eattr, kw1, kb1);
    {
        dim3 g(256, 32);
        gemm_g_kernel<<<g, 256>>>(kw2);
    }
    edgemsg_kernel<<<4096, 128>>>(kb2);

    // combine
    final_kernel<<<4096, 128>>>(root, gbias, out);
}